// round 13
// baseline (speedup 1.0000x reference)
#include <cuda_runtime.h>
#include <cstdint>
#include <cstddef>

// Fixed shapes: n=512, H=512, B=256
#define BB 256
#define HH 512
#define NN 512
#define GBLK 128      // 8 row-groups (jy) x 16 col tiles (jx); 1 block/SM
#define NTHR 256
#define KT   32
#define SP   68       // paired-buffer stride per k (64 payload + 4 pad) -> 16B aligned rows
#define SS   36       // scalar-buffer stride per k (32 + 4 pad)
// stage layout (floats): A(2176) W0(2176) W1(2176) W2(2176) WNS(1152) = 9856
#define OA   0
#define OWP(g) (2176 + (g) * 2176)
#define OWN  8704
#define STGF 9856
#define SMEMF (2 * STGF)        // 19712 floats = 78848 B
#define NEG_INF (-1.0e9f)
#define F32_TINY 1.17549435e-38f

// -------- device scratch (no allocations allowed) --------
__device__ float    g_h0[2][BB * HH];
__device__ float    g_h1[2][BB * HH];
__device__ float    g_logits[BB * NN];
__device__ int      g_sel[BB];
__device__ unsigned g_avail[BB * (NN / 32)];
__device__ float    g_lp[BB];
__device__ float    g_rowsum[3 * HH];
__device__ unsigned g_bar_cnt;
__device__ unsigned g_bar_gen;
__device__ unsigned g_grp_cnt[8];
__device__ unsigned g_grp_gen[8];

// -------- Threefry-2x32 (20 rounds), bit-exact JAX replica --------
__device__ __forceinline__ unsigned rotl32(unsigned v, int r) {
    return (v << r) | (v >> (32 - r));
}

__device__ __forceinline__ void tf2x32(unsigned ks0, unsigned ks1,
                                       unsigned x0, unsigned x1,
                                       unsigned& o0, unsigned& o1)
{
    unsigned ks2 = ks0 ^ ks1 ^ 0x1BD11BDAu;
    x0 += ks0; x1 += ks1;
#define TF_R4(a,b,c,d) \
    x0 += x1; x1 = rotl32(x1,(a)); x1 ^= x0; \
    x0 += x1; x1 = rotl32(x1,(b)); x1 ^= x0; \
    x0 += x1; x1 = rotl32(x1,(c)); x1 ^= x0; \
    x0 += x1; x1 = rotl32(x1,(d)); x1 ^= x0;
    TF_R4(13,15,26,6)   x0 += ks1; x1 += ks2 + 1u;
    TF_R4(17,29,16,24)  x0 += ks2; x1 += ks0 + 2u;
    TF_R4(13,15,26,6)   x0 += ks0; x1 += ks1 + 3u;
    TF_R4(17,29,16,24)  x0 += ks1; x1 += ks2 + 4u;
    TF_R4(13,15,26,6)   x0 += ks2; x1 += ks0 + 5u;
#undef TF_R4
    o0 = x0; o1 = x1;
}

// XLA lowers logistic(x) as 0.5 + 0.5*tanh(0.5*x); mirror that op graph.
__device__ __forceinline__ float jax_sigmoid(float x) {
    return __fadd_rn(0.5f, __fmul_rn(0.5f, tanhf(__fmul_rn(0.5f, x))));
}

__device__ __forceinline__ float4 ldcg4(const float* p) {
    return __ldcg(reinterpret_cast<const float4*>(p));
}
__device__ __forceinline__ float4 ldg4(const float* p) {
    return __ldg(reinterpret_cast<const float4*>(p));
}

// -------- packed f32x2 FMA: two IEEE fp32 FMAs per instruction --------
union f2u { float2 f; unsigned long long u; };

__device__ __forceinline__ float2 ffma2(float2 a, float2 b, float2 c) {
    f2u A, B, C, D;
    A.f = a; B.f = b; C.f = c;
    asm("fma.rn.f32x2 %0, %1, %2, %3;" : "=l"(D.u) : "l"(A.u), "l"(B.u), "l"(C.u));
    return D.f;
}
__device__ __forceinline__ float2 f2lo(float4 v) { return make_float2(v.x, v.y); }
__device__ __forceinline__ float2 f2hi(float4 v) { return make_float2(v.z, v.w); }
__device__ __forceinline__ float2 lds2(const float* p) {
    return *reinterpret_cast<const float2*>(p);
}
__device__ __forceinline__ float4 ld4s(const float* p) {
    return *reinterpret_cast<const float4*>(p);
}
__device__ __forceinline__ void st2(float* p, float a, float b) {
    *reinterpret_cast<float2*>(p) = make_float2(a, b);
}

// staging: thread (lr = elem 0..31, lq = k-quad 0..7) writes 4 k's of elem lr.
// paired store: (u_k, v_k) at [k][2*lr]
#define ST_PAIR(basep, kb, uu, vv, rr) do { \
    st2((basep) + ((kb) + 0) * SP + 2 * (rr), (uu).x, (vv).x); \
    st2((basep) + ((kb) + 1) * SP + 2 * (rr), (uu).y, (vv).y); \
    st2((basep) + ((kb) + 2) * SP + 2 * (rr), (uu).z, (vv).z); \
    st2((basep) + ((kb) + 3) * SP + 2 * (rr), (uu).w, (vv).w); \
} while (0)
// scalar store into stride-SS buffer
#define ST_SCL(basep, kb, vv, rr) do { \
    (basep)[((kb) + 0) * SS + (rr)] = (vv).x; \
    (basep)[((kb) + 1) * SS + (rr)] = (vv).y; \
    (basep)[((kb) + 2) * SS + (rr)] = (vv).z; \
    (basep)[((kb) + 3) * SS + (rr)] = (vv).w; \
} while (0)

// -------- barriers --------
__device__ __forceinline__ void gsync_all() {
    __syncthreads();
    if (threadIdx.x == 0) {
        __threadfence();
        unsigned gen = *(volatile unsigned*)&g_bar_gen;
        if (atomicAdd(&g_bar_cnt, 1u) == GBLK - 1u) {
            atomicExch(&g_bar_cnt, 0u);
            __threadfence();
            atomicAdd(&g_bar_gen, 1u);
        } else {
            while (*(volatile unsigned*)&g_bar_gen == gen) { }
        }
        __threadfence();
    }
    __syncthreads();
}

__device__ __forceinline__ void gsync_grp(int gid) {
    __syncthreads();
    if (threadIdx.x == 0) {
        __threadfence();
        unsigned gen = *(volatile unsigned*)&g_grp_gen[gid];
        if (atomicAdd(&g_grp_cnt[gid], 1u) == 15u) {
            atomicExch(&g_grp_cnt[gid], 0u);
            __threadfence();
            atomicAdd(&g_grp_gen[gid], 1u);
        } else {
            while (*(volatile unsigned*)&g_grp_gen[gid] == gen) { }
        }
        __threadfence();
    }
    __syncthreads();
}

__global__ void __launch_bounds__(NTHR, 1) perm_persistent(
    const float* __restrict__ Wih0, const float* __restrict__ Whh0,
    const float* __restrict__ bih0, const float* __restrict__ bhh0,
    const float* __restrict__ Wih1, const float* __restrict__ Whh1,
    const float* __restrict__ bih1, const float* __restrict__ bhh1,
    const float* __restrict__ Wout, const float* __restrict__ bout,
    float* __restrict__ out)
{
    extern __shared__ __align__(16) float SM[];

    const int blk = blockIdx.x;
    const int tid = threadIdx.x;

    // ---------------- init (per-launch state reset) ----------------
    {
        for (int i = blk * NTHR + tid; i < BB * HH; i += GBLK * NTHR) {
            g_h0[0][i] = 0.0f;
            g_h1[0][i] = 0.0f;
        }
        if (tid < 2) g_lp[2 * blk + tid] = 0.0f;
        if (tid < 32) g_avail[(2 * blk + (tid >> 4)) * 16 + (tid & 15)] = 0xFFFFFFFFu;
        int lane = tid & 31;
        for (int row = blk * 8 + (tid >> 5); row < 3 * HH; row += GBLK * 8) {
            const float* rp = Wih0 + (size_t)row * HH;
            float s = 0.0f;
            for (int k = lane; k < HH; k += 32) s = __fadd_rn(s, rp[k]);
#pragma unroll
            for (int off = 16; off > 0; off >>= 1)
                s = __fadd_rn(s, __shfl_xor_sync(0xFFFFFFFFu, s, off));
            if (lane == 0) g_rowsum[row] = s;
        }
    }
    gsync_all();

    // tiles: blk = jy*16 + jx; group gid = jy (16 blocks, rows closed)
    const int jx = blk & 15, jy = blk >> 4;
    const int gid = jy;
    const int bm0 = jy * 32, jn0 = jx * 32;

    // compute mapping: warp = (wy 0..3 row-group of 8 rows) x (wx 0..1 col-group of 16)
    const int wrp = tid >> 5, lane = tid & 31;
    const int wy = wrp >> 1, wx = wrp & 1;
    const int lty = lane >> 3, ltx = lane & 7;
    const int r0 = wy * 8 + 2 * lty;          // rows r0, r0+1 (even)
    const int c0 = wx * 16 + 2 * ltx;         // cols c0, c0+1 (even)

    // loader mapping: lr = elem 0..31, lq = k-quad 0..7 (k base 4*lq)
    const int lr = tid & 31, lq = tid >> 5;
    const int kb = lq * 4;

    for (int t = 0; t < NN; t++) {
        const int p = t & 1;
        const float* h0_in  = g_h0[p];
        float*       h0_out = g_h0[p ^ 1];
        const float* h1_in  = g_h1[p];
        float*       h1_out = g_h1[p ^ 1];

        // ================ layer 0: h0n = GRU(onehot(sel), h0) ================
        // A: dup act (x,x); W0: (wr,wz) pairs; WN: wn scalar
        {
            float gi[2][3][2];
            if (t == 0) {
#pragma unroll
                for (int ni = 0; ni < 2; ni++) {
                    int j = jn0 + c0 + ni;
                    float v0 = __ldcg(&g_rowsum[j]);
                    float v1 = __ldcg(&g_rowsum[j + HH]);
                    float v2 = __ldcg(&g_rowsum[j + 2 * HH]);
#pragma unroll
                    for (int mi = 0; mi < 2; mi++) {
                        gi[mi][0][ni] = v0; gi[mi][1][ni] = v1; gi[mi][2][ni] = v2;
                    }
                }
            } else {
#pragma unroll
                for (int mi = 0; mi < 2; mi++) {
                    int xs = __ldcg(&g_sel[bm0 + r0 + mi]);
#pragma unroll
                    for (int g = 0; g < 3; g++)
#pragma unroll
                        for (int ni = 0; ni < 2; ni++)
                            gi[mi][g][ni] = __ldg(&Wih0[(size_t)(g * HH + jn0 + c0 + ni) * HH + xs]);
                }
            }

            float2 acc_rz[2][2];   // [row m][col c] lanes = (r-gate, z-gate)
            float2 acc_n[2];       // [row m] lanes = (col c0, col c0+1)
#pragma unroll
            for (int m = 0; m < 2; m++) {
                acc_rz[m][0] = make_float2(0.f, 0.f);
                acc_rz[m][1] = make_float2(0.f, 0.f);
                acc_n[m]     = make_float2(0.f, 0.f);
            }

            const float* asrc = h0_in + (size_t)(bm0 + lr) * HH + kb;
            const float* wrsrc = Whh0 + (size_t)(jn0 + lr) * HH + kb;
            const float* wzsrc = Whh0 + (size_t)(HH + jn0 + lr) * HH + kb;
            const float* wnsrc = Whh0 + (size_t)(2 * HH + jn0 + lr) * HH + kb;

            float4 pa = ldcg4(asrc), pr = ldg4(wrsrc), pz = ldg4(wzsrc), pn = ldg4(wnsrc);
            {
                float* B = SM;
                ST_PAIR(B + OA, kb, pa, pa, lr);
                ST_PAIR(B + OWP(0), kb, pr, pz, lr);
                ST_SCL(B + OWN, kb, pn, lr);
            }
            __syncthreads();

#pragma unroll 1
            for (int tl = 0; tl < 16; tl++) {
                float* BC = SM + (tl & 1) * STGF;
                float* BN = SM + ((tl & 1) ^ 1) * STGF;
                if (tl < 15) {
                    int kn = (tl + 1) * KT;
                    pa = ldcg4(asrc + kn); pr = ldg4(wrsrc + kn);
                    pz = ldg4(wzsrc + kn); pn = ldg4(wnsrc + kn);
                }
#pragma unroll
                for (int k = 0; k < KT; k++) {
                    float4 av = ld4s(BC + OA + k * SP + 2 * r0);        // (x0,x0,x1,x1)
                    float2 a0 = f2lo(av), a1 = f2hi(av);
                    float4 wv = ld4s(BC + OWP(0) + k * SP + 2 * c0);    // (wr0,wz0,wr1,wz1)
                    float2 w0 = f2lo(wv), w1 = f2hi(wv);
                    acc_rz[0][0] = ffma2(a0, w0, acc_rz[0][0]);
                    acc_rz[0][1] = ffma2(a0, w1, acc_rz[0][1]);
                    acc_rz[1][0] = ffma2(a1, w0, acc_rz[1][0]);
                    acc_rz[1][1] = ffma2(a1, w1, acc_rz[1][1]);
                    float2 wn2 = lds2(BC + OWN + k * SS + c0);          // (wn0,wn1)
                    acc_n[0] = ffma2(a0, wn2, acc_n[0]);
                    acc_n[1] = ffma2(a1, wn2, acc_n[1]);
                }
                if (tl < 15) {
                    ST_PAIR(BN + OA, kb, pa, pa, lr);
                    ST_PAIR(BN + OWP(0), kb, pr, pz, lr);
                    ST_SCL(BN + OWN, kb, pn, lr);
                }
                __syncthreads();
            }

#pragma unroll
            for (int mi = 0; mi < 2; mi++) {
                int b = bm0 + r0 + mi;
#pragma unroll
                for (int ni = 0; ni < 2; ni++) {
                    int j = jn0 + c0 + ni;
                    float ir  = __fadd_rn(gi[mi][0][ni], bih0[j]);
                    float iz  = __fadd_rn(gi[mi][1][ni], bih0[j + HH]);
                    float inn = __fadd_rn(gi[mi][2][ni], bih0[j + 2 * HH]);
                    float hr  = __fadd_rn(acc_rz[mi][ni].x, bhh0[j]);
                    float hz  = __fadd_rn(acc_rz[mi][ni].y, bhh0[j + HH]);
                    float hn  = __fadd_rn(ni ? acc_n[mi].y : acc_n[mi].x, bhh0[j + 2 * HH]);
                    float r  = jax_sigmoid(__fadd_rn(ir, hr));
                    float z  = jax_sigmoid(__fadd_rn(iz, hz));
                    float ng = tanhf(__fadd_rn(inn, __fmul_rn(r, hn)));
                    float hp = __ldcg(&h0_in[(size_t)b * HH + j]);
                    h0_out[(size_t)b * HH + j] =
                        __fadd_rn(__fmul_rn(__fsub_rn(1.0f, z), ng), __fmul_rn(z, hp));
                }
            }
        }
        gsync_grp(gid);

        // ================ layer 1: h1n = GRU(h0n, h1) ================
        // A: (x,h) pairs; W0..2: (wI_g, wH_g) pairs
        {
            float2 acc[3][2][2];   // [gate][row m][col c] lanes = (I-sum, H-sum)
#pragma unroll
            for (int g = 0; g < 3; g++)
#pragma unroll
                for (int m = 0; m < 2; m++) {
                    acc[g][m][0] = make_float2(0.f, 0.f);
                    acc[g][m][1] = make_float2(0.f, 0.f);
                }

            const float* xsrc = h0_out + (size_t)(bm0 + lr) * HH + kb;
            const float* hsrc = h1_in  + (size_t)(bm0 + lr) * HH + kb;
            const float* wisrc[3];
            const float* whsrc[3];
#pragma unroll
            for (int g = 0; g < 3; g++) {
                wisrc[g] = Wih1 + (size_t)(g * HH + jn0 + lr) * HH + kb;
                whsrc[g] = Whh1 + (size_t)(g * HH + jn0 + lr) * HH + kb;
            }

            float4 px = ldcg4(xsrc), ph = ldcg4(hsrc);
            float4 pwi[3], pwh[3];
#pragma unroll
            for (int g = 0; g < 3; g++) { pwi[g] = ldg4(wisrc[g]); pwh[g] = ldg4(whsrc[g]); }
            {
                float* B = SM;
                ST_PAIR(B + OA, kb, px, ph, lr);
#pragma unroll
                for (int g = 0; g < 3; g++) ST_PAIR(B + OWP(g), kb, pwi[g], pwh[g], lr);
            }
            __syncthreads();

#pragma unroll 1
            for (int tl = 0; tl < 16; tl++) {
                float* BC = SM + (tl & 1) * STGF;
                float* BN = SM + ((tl & 1) ^ 1) * STGF;
                if (tl < 15) {
                    int kn = (tl + 1) * KT;
                    px = ldcg4(xsrc + kn); ph = ldcg4(hsrc + kn);
#pragma unroll
                    for (int g = 0; g < 3; g++) { pwi[g] = ldg4(wisrc[g] + kn); pwh[g] = ldg4(whsrc[g] + kn); }
                }
#pragma unroll
                for (int k = 0; k < KT; k++) {
                    float4 av = ld4s(BC + OA + k * SP + 2 * r0);        // (x0,h0,x1,h1)
                    float2 a0 = f2lo(av), a1 = f2hi(av);
#pragma unroll
                    for (int g = 0; g < 3; g++) {
                        float4 wv = ld4s(BC + OWP(g) + k * SP + 2 * c0); // (wI0,wH0,wI1,wH1)
                        float2 w0 = f2lo(wv), w1 = f2hi(wv);
                        acc[g][0][0] = ffma2(a0, w0, acc[g][0][0]);
                        acc[g][0][1] = ffma2(a0, w1, acc[g][0][1]);
                        acc[g][1][0] = ffma2(a1, w0, acc[g][1][0]);
                        acc[g][1][1] = ffma2(a1, w1, acc[g][1][1]);
                    }
                }
                if (tl < 15) {
                    ST_PAIR(BN + OA, kb, px, ph, lr);
#pragma unroll
                    for (int g = 0; g < 3; g++) ST_PAIR(BN + OWP(g), kb, pwi[g], pwh[g], lr);
                }
                __syncthreads();
            }

#pragma unroll
            for (int mi = 0; mi < 2; mi++) {
#pragma unroll
                for (int ni = 0; ni < 2; ni++) {
                    int b = bm0 + r0 + mi;
                    int j = jn0 + c0 + ni;
                    float ir  = __fadd_rn(acc[0][mi][ni].x, bih1[j]);
                    float hr  = __fadd_rn(acc[0][mi][ni].y, bhh1[j]);
                    float iz  = __fadd_rn(acc[1][mi][ni].x, bih1[j + HH]);
                    float hz  = __fadd_rn(acc[1][mi][ni].y, bhh1[j + HH]);
                    float inn = __fadd_rn(acc[2][mi][ni].x, bih1[j + 2 * HH]);
                    float hn  = __fadd_rn(acc[2][mi][ni].y, bhh1[j + 2 * HH]);
                    float r  = jax_sigmoid(__fadd_rn(ir, hr));
                    float z  = jax_sigmoid(__fadd_rn(iz, hz));
                    float ng = tanhf(__fadd_rn(inn, __fmul_rn(r, hn)));
                    float hp = __ldcg(&h1_in[(size_t)b * HH + j]);
                    h1_out[(size_t)b * HH + j] =
                        __fadd_rn(__fmul_rn(__fsub_rn(1.0f, z), ng), __fmul_rn(z, hp));
                }
            }
        }
        gsync_grp(gid);

        // ================ logits = h1n @ W_out^T + b_out ================
        // A: dup act (x,x); WN: wout scalar
        {
            float2 acc[2];   // [row m] lanes = (col c0, col c0+1)
            acc[0] = make_float2(0.f, 0.f); acc[1] = make_float2(0.f, 0.f);

            const float* asrc = h1_out + (size_t)(bm0 + lr) * HH + kb;
            const float* wsrc = Wout + (size_t)(jn0 + lr) * HH + kb;

            float4 pa = ldcg4(asrc), pw = ldg4(wsrc);
            {
                float* B = SM;
                ST_PAIR(B + OA, kb, pa, pa, lr);
                ST_SCL(B + OWN, kb, pw, lr);
            }
            __syncthreads();

#pragma unroll 1
            for (int tl = 0; tl < 16; tl++) {
                float* BC = SM + (tl & 1) * STGF;
                float* BN = SM + ((tl & 1) ^ 1) * STGF;
                if (tl < 15) {
                    int kn = (tl + 1) * KT;
                    pa = ldcg4(asrc + kn); pw = ldg4(wsrc + kn);
                }
#pragma unroll
                for (int k = 0; k < KT; k++) {
                    float4 av = ld4s(BC + OA + k * SP + 2 * r0);
                    float2 a0 = f2lo(av), a1 = f2hi(av);
                    float2 w2 = lds2(BC + OWN + k * SS + c0);
                    acc[0] = ffma2(a0, w2, acc[0]);
                    acc[1] = ffma2(a1, w2, acc[1]);
                }
                if (tl < 15) {
                    ST_PAIR(BN + OA, kb, pa, pa, lr);
                    ST_SCL(BN + OWN, kb, pw, lr);
                }
                __syncthreads();
            }
#pragma unroll
            for (int mi = 0; mi < 2; mi++)
#pragma unroll
                for (int ni = 0; ni < 2; ni++) {
                    int b = bm0 + r0 + mi;
                    int c = jn0 + c0 + ni;
                    g_logits[(size_t)b * NN + c] =
                        __fadd_rn(ni ? acc[mi].y : acc[mi].x, bout[c]);
                }
        }
        gsync_grp(gid);

        // ===== sample: 2 batch rows per block (128 threads each), shuffle reductions =====
        {
            float* SSv = SM;                  // [2][4]
            int*   SSi = (int*)(SM + 8);      // [2][4]
            float* SVm = SM + 16;             // [2][4]
            float* SEx = SM + 24;             // [2][4]

            const int r   = tid >> 7;
            const int cc  = tid & 127;
            const int wir = (tid >> 5) & 3;
            const int b   = 2 * blk + r;

            unsigned sk0, sk1;
            tf2x32(0u, 42u, 0u, (unsigned)t, sk0, sk1);

            float vq[4];
            float bs = -3.4e38f; int bi = 0;
            float lv = -3.4e38f;
#pragma unroll
            for (int q = 0; q < 4; q++) {
                int col = cc + 128 * q;
                float lg = __ldcg(&g_logits[(size_t)b * NN + col]);
                unsigned w = g_avail[b * 16 + (col >> 5)];
                float v = ((w >> (col & 31)) & 1u) ? lg : NEG_INF;
                vq[q] = v;
                unsigned o0, o1;
                tf2x32(sk0, sk1, 0u, (unsigned)(b * NN + col), o0, o1);
                unsigned bits = o0 ^ o1;
                float f = __fsub_rn(__uint_as_float((bits >> 9) | 0x3F800000u), 1.0f);
                float gmb = -logf(-logf(fmaxf(f, F32_TINY)));
                float s = __fadd_rn(gmb, v);
                if (s > bs || (s == bs && col < bi)) { bs = s; bi = col; }
                lv = fmaxf(lv, v);
            }
#pragma unroll
            for (int off = 16; off > 0; off >>= 1) {
                float os = __shfl_xor_sync(0xFFFFFFFFu, bs, off);
                int   oi = __shfl_xor_sync(0xFFFFFFFFu, bi, off);
                float ov = __shfl_xor_sync(0xFFFFFFFFu, lv, off);
                if (os > bs || (os == bs && oi < bi)) { bs = os; bi = oi; }
                lv = fmaxf(lv, ov);
            }
            if ((tid & 31) == 0) {
                SSv[r * 4 + wir] = bs; SSi[r * 4 + wir] = bi; SVm[r * 4 + wir] = lv;
            }
            __syncthreads();

            float vmax = SVm[r * 4];
#pragma unroll
            for (int w = 1; w < 4; w++) vmax = fmaxf(vmax, SVm[r * 4 + w]);

            float es = 0.0f;
#pragma unroll
            for (int q = 0; q < 4; q++)
                es = __fadd_rn(es, expf(__fsub_rn(vq[q], vmax)));
#pragma unroll
            for (int off = 16; off > 0; off >>= 1)
                es = __fadd_rn(es, __shfl_xor_sync(0xFFFFFFFFu, es, off));
            if ((tid & 31) == 0) SEx[r * 4 + wir] = es;
            __syncthreads();

            if (cc == 0) {
                float fs = SSv[r * 4]; int fi = SSi[r * 4];
                float S  = SEx[r * 4];
#pragma unroll
                for (int w = 1; w < 4; w++) {
                    float os = SSv[r * 4 + w]; int oi = SSi[r * 4 + w];
                    if (os > fs || (os == fs && oi < fi)) { fs = os; fi = oi; }
                    S = __fadd_rn(S, SEx[r * 4 + w]);
                }
                int idx = fi;
                float vsel = __ldcg(&g_logits[(size_t)b * NN + idx]);   // idx is available
                float ps = __fdiv_rn(expf(__fsub_rn(vsel, vmax)), S);
                float lp = __fadd_rn(g_lp[b], logf(__fadd_rn(ps, 1e-9f)));
                g_lp[b]  = lp;
                g_sel[b] = idx;
                g_avail[b * 16 + (idx >> 5)] &= ~(1u << (idx & 31));
                out[(size_t)b * NN * NN + (size_t)t * NN + idx] = 1.0f;
                if (t == NN - 1) out[(size_t)BB * NN * NN + b] = lp;
            }
        }
        gsync_grp(gid);
    }
}

// -------- host launcher: 2 graph nodes (memset + persistent kernel) --------
extern "C" void kernel_launch(void* const* d_in, const int* in_sizes, int n_in,
                              void* d_out, int out_size)
{
    int base = (n_in == 11) ? 1 : 0;   // batch_size scalar first per metadata
    const float* Wih0 = (const float*)d_in[base + 0];
    const float* Whh0 = (const float*)d_in[base + 1];
    const float* bih0 = (const float*)d_in[base + 2];
    const float* bhh0 = (const float*)d_in[base + 3];
    const float* Wih1 = (const float*)d_in[base + 4];
    const float* Whh1 = (const float*)d_in[base + 5];
    const float* bih1 = (const float*)d_in[base + 6];
    const float* bhh1 = (const float*)d_in[base + 7];
    const float* Wout = (const float*)d_in[base + 8];
    const float* bout = (const float*)d_in[base + 9];
    float* out = (float*)d_out;
    (void)in_sizes;

    size_t shbytes = (size_t)SMEMF * sizeof(float);   // 78848 B
    cudaFuncSetAttribute(perm_persistent,
                         cudaFuncAttributeMaxDynamicSharedMemorySize, (int)shbytes);

    cudaMemsetAsync(d_out, 0, (size_t)out_size * sizeof(float), 0);
    perm_persistent<<<GBLK, NTHR, shbytes>>>(Wih0, Whh0, bih0, bhh0,
                                             Wih1, Whh1, bih1, bhh1,
                                             Wout, bout, out);
}

// round 16
// speedup vs baseline: 1.3958x; 1.3958x over previous
#include <cuda_runtime.h>
#include <cstdint>
#include <cstddef>

// Fixed shapes: n=512, H=512, B=256
#define BB 256
#define HH 512
#define NN 512
#define GBLK 128      // 8 row-groups (jy; 16 blocks, 32 rows) x 16 col tiles (jx)
#define NTHR 256
#define TS 34         // smem stride (R8 layout)
#define NEG_INF (-1.0e9f)
#define F32_TINY 1.17549435e-38f

// -------- device scratch (no allocations allowed) --------
__device__ float    g_h0[2][BB * HH];
__device__ float    g_h1[2][BB * HH];
__device__ float    g_logits[BB * NN];
__device__ int      g_sel[BB];
__device__ unsigned g_avail[BB * (NN / 32)];
__device__ float    g_lp[BB];
__device__ float    g_rowsum[3 * HH];
__device__ unsigned g_bar_cnt;            // global barrier (init only)
__device__ unsigned g_bar_gen;
__device__ unsigned g_grp_cnt[8 * 32];    // per-group, 128B apart
__device__ unsigned g_grp_gen[8 * 32];

// -------- Threefry-2x32 (20 rounds), bit-exact JAX replica --------
__device__ __forceinline__ unsigned rotl32(unsigned v, int r) {
    return (v << r) | (v >> (32 - r));
}

__device__ __forceinline__ void tf2x32(unsigned ks0, unsigned ks1,
                                       unsigned x0, unsigned x1,
                                       unsigned& o0, unsigned& o1)
{
    unsigned ks2 = ks0 ^ ks1 ^ 0x1BD11BDAu;
    x0 += ks0; x1 += ks1;
#define TF_R4(a,b,c,d) \
    x0 += x1; x1 = rotl32(x1,(a)); x1 ^= x0; \
    x0 += x1; x1 = rotl32(x1,(b)); x1 ^= x0; \
    x0 += x1; x1 = rotl32(x1,(c)); x1 ^= x0; \
    x0 += x1; x1 = rotl32(x1,(d)); x1 ^= x0;
    TF_R4(13,15,26,6)   x0 += ks1; x1 += ks2 + 1u;
    TF_R4(17,29,16,24)  x0 += ks2; x1 += ks0 + 2u;
    TF_R4(13,15,26,6)   x0 += ks0; x1 += ks1 + 3u;
    TF_R4(17,29,16,24)  x0 += ks1; x1 += ks2 + 4u;
    TF_R4(13,15,26,6)   x0 += ks2; x1 += ks0 + 5u;
#undef TF_R4
    o0 = x0; o1 = x1;
}

// XLA lowers logistic(x) as 0.5 + 0.5*tanh(0.5*x); mirror that op graph.
__device__ __forceinline__ float jax_sigmoid(float x) {
    return __fadd_rn(0.5f, __fmul_rn(0.5f, tanhf(__fmul_rn(0.5f, x))));
}

__device__ __forceinline__ float4 ldcg4(const float* p) {
    return __ldcg(reinterpret_cast<const float4*>(p));
}

// -------- packed f32x2 FMA: two IEEE fp32 FMAs per instruction --------
union f2u { float2 f; unsigned long long u; };

__device__ __forceinline__ float2 ffma2(float2 a, float2 b, float2 c) {
    f2u A, B, C, D;
    A.f = a; B.f = b; C.f = c;
    asm("fma.rn.f32x2 %0, %1, %2, %3;" : "=l"(D.u) : "l"(A.u), "l"(B.u), "l"(C.u));
    return D.f;
}
__device__ __forceinline__ float2 bc2(float a) { return make_float2(a, a); }

// transposed smem store of a k-direction float4 (R8 layout)
__device__ __forceinline__ void st_tr(float* buf, int lc, int lr, float4 v) {
    buf[(lc + 0) * TS + lr] = v.x;
    buf[(lc + 1) * TS + lr] = v.y;
    buf[(lc + 2) * TS + lr] = v.z;
    buf[(lc + 3) * TS + lr] = v.w;
}
__device__ __forceinline__ float2 lds2(const float* p) {
    return *reinterpret_cast<const float2*>(p);
}

// -------- barriers --------
__device__ __forceinline__ void gsync_all() {
    __syncthreads();
    if (threadIdx.x == 0) {
        __threadfence();
        unsigned gen = *(volatile unsigned*)&g_bar_gen;
        if (atomicAdd(&g_bar_cnt, 1u) == GBLK - 1u) {
            atomicExch(&g_bar_cnt, 0u);
            __threadfence();
            atomicAdd(&g_bar_gen, 1u);
        } else {
            while (*(volatile unsigned*)&g_bar_gen == gen) { }
        }
        __threadfence();
    }
    __syncthreads();
}

// 16-block group barrier; padded state lines per group
__device__ __forceinline__ void gsync_grp(int gid) {
    __syncthreads();
    if (threadIdx.x == 0) {
        __threadfence();
        unsigned* cnt = &g_grp_cnt[gid * 32];
        unsigned* gen = &g_grp_gen[gid * 32];
        unsigned g0 = *(volatile unsigned*)gen;
        if (atomicAdd(cnt, 1u) == 15u) {
            atomicExch(cnt, 0u);
            __threadfence();
            atomicAdd(gen, 1u);
        } else {
            while (*(volatile unsigned*)gen == g0) { }
        }
        __threadfence();
    }
    __syncthreads();
}

#define SMBUF(i) (SM + (i) * (32 * TS))

__global__ void __launch_bounds__(NTHR, 1) perm_persistent(
    const float* __restrict__ Wih0, const float* __restrict__ Whh0,
    const float* __restrict__ bih0, const float* __restrict__ bhh0,
    const float* __restrict__ Wih1, const float* __restrict__ Whh1,
    const float* __restrict__ bih1, const float* __restrict__ bhh1,
    const float* __restrict__ Wout, const float* __restrict__ bout,
    float* __restrict__ out)
{
    __shared__ float SM[8 * 32 * TS];   // 34.8 KB, unioned across phases

    const int blk = blockIdx.x;
    const int tid = threadIdx.x;

    // ---------------- init (per-launch state reset) ----------------
    {
        for (int i = blk * NTHR + tid; i < BB * HH; i += GBLK * NTHR) {
            g_h0[0][i] = 0.0f;
            g_h1[0][i] = 0.0f;
        }
        if (tid < 2) g_lp[2 * blk + tid] = 0.0f;
        if (tid < 32) g_avail[(2 * blk + (tid >> 4)) * 16 + (tid & 15)] = 0xFFFFFFFFu;
        int lane = tid & 31;
        for (int row = blk * 8 + (tid >> 5); row < 3 * HH; row += GBLK * 8) {
            const float* rp = Wih0 + (size_t)row * HH;
            float s = 0.0f;
            for (int k = lane; k < HH; k += 32) s = __fadd_rn(s, rp[k]);
#pragma unroll
            for (int off = 16; off > 0; off >>= 1)
                s = __fadd_rn(s, __shfl_xor_sync(0xFFFFFFFFu, s, off));
            if (lane == 0) g_rowsum[row] = s;
        }
    }
    gsync_all();

    // tile jobs: 8 row-groups (32 rows) x 16 col tiles (32 cols)
    const int jx = blk & 15;
    const int jy = blk >> 4;
    const int gid = jy;
    const int bm0 = jy * 32;
    const int jn0 = jx * 32;
    const int tx = tid & 15, ty = tid >> 4;       // compute: rows 2ty,2ty+1 ; cols 2tx,2tx+1
    const int lr = tid >> 3, lc = (tid & 7) << 2; // loader

    // ---------------- bootstrap: h0n(0) (h0 = 0 -> GEMM term exactly 0) ----------------
    {
        float* h_out = g_h0[1];
#pragma unroll
        for (int mi = 0; mi < 2; mi++) {
            int b = bm0 + 2 * ty + mi;
#pragma unroll
            for (int ni = 0; ni < 2; ni++) {
                int j = jn0 + 2 * tx + ni;
                float ir  = __fadd_rn(__ldcg(&g_rowsum[j]),          bih0[j]);
                float iz  = __fadd_rn(__ldcg(&g_rowsum[j + HH]),     bih0[j + HH]);
                float inn = __fadd_rn(__ldcg(&g_rowsum[j + 2 * HH]), bih0[j + 2 * HH]);
                float hr = __fadd_rn(0.0f, bhh0[j]);
                float hz = __fadd_rn(0.0f, bhh0[j + HH]);
                float hn = __fadd_rn(0.0f, bhh0[j + 2 * HH]);
                float r  = jax_sigmoid(__fadd_rn(ir, hr));
                float z  = jax_sigmoid(__fadd_rn(iz, hz));
                float ng = tanhf(__fadd_rn(inn, __fmul_rn(r, hn)));
                h_out[(size_t)b * HH + j] =
                    __fadd_rn(__fmul_rn(__fsub_rn(1.0f, z), ng), __fmul_rn(z, 0.0f));
            }
        }
    }
    gsync_grp(gid);

    for (int t = 0; t < NN; t++) {
        const int p = t & 1;

        // ================ layer 1 (t): h1n = GRU(h0n(t), h1) ================
        {
            const float* x_in  = g_h0[p ^ 1];
            const float* h_in  = g_h1[p];
            float*       h_out = g_h1[p ^ 1];

            float2 accI[3][2], accH[3][2];
#pragma unroll
            for (int g = 0; g < 3; g++) {
                accI[g][0] = make_float2(0.f, 0.f); accI[g][1] = make_float2(0.f, 0.f);
                accH[g][0] = make_float2(0.f, 0.f); accH[g][1] = make_float2(0.f, 0.f);
            }
            float4 pa0 = ldcg4(x_in + (size_t)(bm0 + lr) * HH + lc);
            float4 pa1 = ldcg4(h_in + (size_t)(bm0 + lr) * HH + lc);
            float4 pw[6];
#pragma unroll
            for (int g = 0; g < 3; g++) {
                pw[g]   = *reinterpret_cast<const float4*>(Wih1 + (size_t)(g * HH + jn0 + lr) * HH + lc);
                pw[3+g] = *reinterpret_cast<const float4*>(Whh1 + (size_t)(g * HH + jn0 + lr) * HH + lc);
            }
#pragma unroll 1
            for (int k0 = 0; k0 < HH; k0 += 32) {
                st_tr(SMBUF(0), lc, lr, pa0);
                st_tr(SMBUF(1), lc, lr, pa1);
#pragma unroll
                for (int g = 0; g < 6; g++) st_tr(SMBUF(2 + g), lc, lr, pw[g]);
                __syncthreads();
                if (k0 + 32 < HH) {
                    int kn = k0 + 32;
                    pa0 = ldcg4(x_in + (size_t)(bm0 + lr) * HH + kn + lc);
                    pa1 = ldcg4(h_in + (size_t)(bm0 + lr) * HH + kn + lc);
#pragma unroll
                    for (int g = 0; g < 3; g++) {
                        pw[g]   = *reinterpret_cast<const float4*>(Wih1 + (size_t)(g * HH + jn0 + lr) * HH + kn + lc);
                        pw[3+g] = *reinterpret_cast<const float4*>(Whh1 + (size_t)(g * HH + jn0 + lr) * HH + kn + lc);
                    }
                }
#pragma unroll
                for (int k = 0; k < 32; k++) {
                    float2 xv = lds2(SMBUF(0) + k * TS + 2 * ty);
                    float2 hv = lds2(SMBUF(1) + k * TS + 2 * ty);
                    float2 x0 = bc2(xv.x), x1 = bc2(xv.y);
                    float2 h0b = bc2(hv.x), h1b = bc2(hv.y);
#pragma unroll
                    for (int g = 0; g < 3; g++) {
                        float2 bw = lds2(SMBUF(2 + g) + k * TS + 2 * tx);
                        accI[g][0] = ffma2(x0, bw, accI[g][0]);
                        accI[g][1] = ffma2(x1, bw, accI[g][1]);
                        float2 cw = lds2(SMBUF(5 + g) + k * TS + 2 * tx);
                        accH[g][0] = ffma2(h0b, cw, accH[g][0]);
                        accH[g][1] = ffma2(h1b, cw, accH[g][1]);
                    }
                }
                __syncthreads();
            }
#pragma unroll
            for (int mi = 0; mi < 2; mi++) {
#pragma unroll
                for (int ni = 0; ni < 2; ni++) {
                    int b = bm0 + 2 * ty + mi;
                    int j = jn0 + 2 * tx + ni;
                    float ir  = __fadd_rn(ni ? accI[0][mi].y : accI[0][mi].x, bih1[j]);
                    float iz  = __fadd_rn(ni ? accI[1][mi].y : accI[1][mi].x, bih1[j + HH]);
                    float inn = __fadd_rn(ni ? accI[2][mi].y : accI[2][mi].x, bih1[j + 2 * HH]);
                    float hr  = __fadd_rn(ni ? accH[0][mi].y : accH[0][mi].x, bhh1[j]);
                    float hz  = __fadd_rn(ni ? accH[1][mi].y : accH[1][mi].x, bhh1[j + HH]);
                    float hn  = __fadd_rn(ni ? accH[2][mi].y : accH[2][mi].x, bhh1[j + 2 * HH]);
                    float r  = jax_sigmoid(__fadd_rn(ir, hr));
                    float z  = jax_sigmoid(__fadd_rn(iz, hz));
                    float ng = tanhf(__fadd_rn(inn, __fmul_rn(r, hn)));
                    float hp = __ldcg(&h_in[(size_t)b * HH + j]);
                    h_out[(size_t)b * HH + j] =
                        __fadd_rn(__fmul_rn(__fsub_rn(1.0f, z), ng), __fmul_rn(z, hp));
                }
            }
        }
        gsync_grp(gid);

        // ================ logits (t) = h1n @ W_out^T + b_out ================
        {
            const float* h = g_h1[p ^ 1];
            float2 acc[2];
            acc[0] = make_float2(0.f, 0.f); acc[1] = make_float2(0.f, 0.f);
            float4 pa = ldcg4(h + (size_t)(bm0 + lr) * HH + lc);
            float4 pb = *reinterpret_cast<const float4*>(Wout + (size_t)(jn0 + lr) * HH + lc);
#pragma unroll 1
            for (int k0 = 0; k0 < HH; k0 += 32) {
                st_tr(SMBUF(0), lc, lr, pa);
                st_tr(SMBUF(1), lc, lr, pb);
                __syncthreads();
                if (k0 + 32 < HH) {
                    int kn = k0 + 32;
                    pa = ldcg4(h + (size_t)(bm0 + lr) * HH + kn + lc);
                    pb = *reinterpret_cast<const float4*>(Wout + (size_t)(jn0 + lr) * HH + kn + lc);
                }
#pragma unroll
                for (int k = 0; k < 32; k++) {
                    float2 av = lds2(SMBUF(0) + k * TS + 2 * ty);
                    float2 bw = lds2(SMBUF(1) + k * TS + 2 * tx);
                    acc[0] = ffma2(bc2(av.x), bw, acc[0]);
                    acc[1] = ffma2(bc2(av.y), bw, acc[1]);
                }
                __syncthreads();
            }
#pragma unroll
            for (int mi = 0; mi < 2; mi++)
#pragma unroll
                for (int ni = 0; ni < 2; ni++) {
                    int b = bm0 + 2 * ty + mi;
                    int c = jn0 + 2 * tx + ni;
                    g_logits[(size_t)b * NN + c] =
                        __fadd_rn(ni ? acc[mi].y : acc[mi].x, bout[c]);
                }
        }
        gsync_grp(gid);

        // ===== phase C: sample(t), then layer0-GEMM(t+1) overlapped =====
        {
            float* W_S = SM;                 // [2][4]
            int*   W_I = (int*)(SM + 8);
            float* W_V = SM + 16;
            float* W_E = SM + 24;
            float* VV  = SM + 64;            // [2][512] masked logits

            const int r    = tid >> 7;
            const int c0   = tid & 127;
            const int wip  = (tid >> 5) & 3;
            const int b    = 2 * blk + r;

            unsigned sk0, sk1;
            tf2x32(0u, 42u, 0u, (unsigned)t, sk0, sk1);

            float vq[4];
            float bs = -3.4e38f; int bi = 0;
            float lv = -3.4e38f;
#pragma unroll
            for (int q = 0; q < 4; q++) {
                int col = c0 + 128 * q;
                float lg = __ldcg(&g_logits[(size_t)b * NN + col]);
                unsigned w = g_avail[b * 16 + (col >> 5)];
                float v = ((w >> (col & 31)) & 1u) ? lg : NEG_INF;
                vq[q] = v;
                VV[r * NN + col] = v;
                unsigned o0, o1;
                tf2x32(sk0, sk1, 0u, (unsigned)(b * NN + col), o0, o1);
                unsigned bits = o0 ^ o1;
                float f = __fsub_rn(__uint_as_float((bits >> 9) | 0x3F800000u), 1.0f);
                float gmb = -logf(-logf(fmaxf(f, F32_TINY)));
                float s = __fadd_rn(gmb, v);
                if (s > bs || (s == bs && col < bi)) { bs = s; bi = col; }
                lv = fmaxf(lv, v);
            }
#pragma unroll
            for (int off = 16; off > 0; off >>= 1) {
                float os = __shfl_xor_sync(0xFFFFFFFFu, bs, off);
                int   oi = __shfl_xor_sync(0xFFFFFFFFu, bi, off);
                float ov = __shfl_xor_sync(0xFFFFFFFFu, lv, off);
                if (os > bs || (os == bs && oi < bi)) { bs = os; bi = oi; }
                lv = fmaxf(lv, ov);
            }
            if ((tid & 31) == 0) {
                W_S[r * 4 + wip] = bs; W_I[r * 4 + wip] = bi; W_V[r * 4 + wip] = lv;
            }
            __syncthreads();
            float vmax = W_V[r * 4];
            float fs = W_S[r * 4]; int fi = W_I[r * 4];
#pragma unroll
            for (int w = 1; w < 4; w++) {
                float os = W_S[r * 4 + w]; int oi = W_I[r * 4 + w];
                if (os > fs || (os == fs && oi < fi)) { fs = os; fi = oi; }
                vmax = fmaxf(vmax, W_V[r * 4 + w]);
            }
            float es = 0.0f;
#pragma unroll
            for (int q = 0; q < 4; q++)
                es = __fadd_rn(es, expf(__fsub_rn(vq[q], vmax)));
#pragma unroll
            for (int off = 16; off > 0; off >>= 1)
                es = __fadd_rn(es, __shfl_xor_sync(0xFFFFFFFFu, es, off));
            if ((tid & 31) == 0) W_E[r * 4 + wip] = es;
            __syncthreads();

            if (c0 == 0) {
                float S = __fadd_rn(__fadd_rn(W_E[r * 4], W_E[r * 4 + 1]),
                                    __fadd_rn(W_E[r * 4 + 2], W_E[r * 4 + 3]));
                int idx = fi;
                float ps = __fdiv_rn(expf(__fsub_rn(VV[r * NN + idx], vmax)), S);
                float lp = __fadd_rn(g_lp[b], logf(__fadd_rn(ps, 1e-9f)));
                g_lp[b]  = lp;
                g_sel[b] = idx;
                g_avail[b * 16 + (idx >> 5)] &= ~(1u << (idx & 31));
                out[(size_t)b * NN * NN + (size_t)t * NN + idx] = 1.0f;
                if (t == NN - 1) out[(size_t)BB * NN * NN + b] = lp;
            }
        }
        __syncthreads();   // SM reuse: sample scratch -> GEMM staging

        // ---- layer0-GEMM(t+1): acc = h0n(t) @ Whh0^T (tile) ----
        float2 acc0[3][2];
#pragma unroll
        for (int g = 0; g < 3; g++) { acc0[g][0] = make_float2(0.f, 0.f); acc0[g][1] = make_float2(0.f, 0.f); }
        if (t < NN - 1) {
            const float* h_in = g_h0[p ^ 1];   // h0n(t)
            float4 pa  = ldcg4(h_in + (size_t)(bm0 + lr) * HH + lc);
            float4 pb0 = *reinterpret_cast<const float4*>(Whh0 + (size_t)(jn0 + lr) * HH + lc);
            float4 pb1 = *reinterpret_cast<const float4*>(Whh0 + (size_t)(HH + jn0 + lr) * HH + lc);
            float4 pb2 = *reinterpret_cast<const float4*>(Whh0 + (size_t)(2 * HH + jn0 + lr) * HH + lc);
#pragma unroll 1
            for (int k0 = 0; k0 < HH; k0 += 32) {
                st_tr(SMBUF(0), lc, lr, pa);
                st_tr(SMBUF(1), lc, lr, pb0);
                st_tr(SMBUF(2), lc, lr, pb1);
                st_tr(SMBUF(3), lc, lr, pb2);
                __syncthreads();
                if (k0 + 32 < HH) {
                    int kn = k0 + 32;
                    pa  = ldcg4(h_in + (size_t)(bm0 + lr) * HH + kn + lc);
                    pb0 = *reinterpret_cast<const float4*>(Whh0 + (size_t)(jn0 + lr) * HH + kn + lc);
                    pb1 = *reinterpret_cast<const float4*>(Whh0 + (size_t)(HH + jn0 + lr) * HH + kn + lc);
                    pb2 = *reinterpret_cast<const float4*>(Whh0 + (size_t)(2 * HH + jn0 + lr) * HH + kn + lc);
                }
#pragma unroll
                for (int k = 0; k < 32; k++) {
                    float2 av = lds2(SMBUF(0) + k * TS + 2 * ty);
                    float2 a0 = bc2(av.x), a1 = bc2(av.y);
#pragma unroll
                    for (int g = 0; g < 3; g++) {
                        float2 bw = lds2(SMBUF(1 + g) + k * TS + 2 * tx);
                        acc0[g][0] = ffma2(a0, bw, acc0[g][0]);
                        acc0[g][1] = ffma2(a1, bw, acc0[g][1]);
                    }
                }
                __syncthreads();
            }
        }
        gsync_grp(gid);   // publishes sel(t); acc0 carried in registers

        // ---- layer0 gather + epilogue (t+1): writes h0n(t+1) ----
        if (t < NN - 1) {
            const float* h_in = g_h0[p ^ 1];
            float*       h_out = g_h0[p];
#pragma unroll
            for (int mi = 0; mi < 2; mi++) {
                int b = bm0 + 2 * ty + mi;
                int xs = __ldcg(&g_sel[b]);
#pragma unroll
                for (int ni = 0; ni < 2; ni++) {
                    int j = jn0 + 2 * tx + ni;
                    float ir  = __ldg(&Wih0[(size_t)j * HH + xs]);
                    float iz  = __ldg(&Wih0[(size_t)(j + HH) * HH + xs]);
                    float inn = __ldg(&Wih0[(size_t)(j + 2 * HH) * HH + xs]);
                    ir  = __fadd_rn(ir,  bih0[j]);
                    iz  = __fadd_rn(iz,  bih0[j + HH]);
                    inn = __fadd_rn(inn, bih0[j + 2 * HH]);
                    float hr = __fadd_rn(ni ? acc0[0][mi].y : acc0[0][mi].x, bhh0[j]);
                    float hz = __fadd_rn(ni ? acc0[1][mi].y : acc0[1][mi].x, bhh0[j + HH]);
                    float hn = __fadd_rn(ni ? acc0[2][mi].y : acc0[2][mi].x, bhh0[j + 2 * HH]);
                    float r  = jax_sigmoid(__fadd_rn(ir, hr));
                    float z  = jax_sigmoid(__fadd_rn(iz, hz));
                    float ng = tanhf(__fadd_rn(inn, __fmul_rn(r, hn)));
                    float hp = __ldcg(&h_in[(size_t)b * HH + j]);
                    h_out[(size_t)b * HH + j] =
                        __fadd_rn(__fmul_rn(__fsub_rn(1.0f, z), ng), __fmul_rn(z, hp));
                }
            }
            gsync_grp(gid);
        }
    }
}

// -------- host launcher: 2 graph nodes (memset + persistent kernel) --------
extern "C" void kernel_launch(void* const* d_in, const int* in_sizes, int n_in,
                              void* d_out, int out_size)
{
    int base = (n_in == 11) ? 1 : 0;   // batch_size scalar first per metadata
    const float* Wih0 = (const float*)d_in[base + 0];
    const float* Whh0 = (const float*)d_in[base + 1];
    const float* bih0 = (const float*)d_in[base + 2];
    const float* bhh0 = (const float*)d_in[base + 3];
    const float* Wih1 = (const float*)d_in[base + 4];
    const float* Whh1 = (const float*)d_in[base + 5];
    const float* bih1 = (const float*)d_in[base + 6];
    const float* bhh1 = (const float*)d_in[base + 7];
    const float* Wout = (const float*)d_in[base + 8];
    const float* bout = (const float*)d_in[base + 9];
    float* out = (float*)d_out;
    (void)in_sizes;

    cudaMemsetAsync(d_out, 0, (size_t)out_size * sizeof(float), 0);
    perm_persistent<<<GBLK, NTHR>>>(Wih0, Whh0, bih0, bhh0,
                                    Wih1, Whh1, bih1, bhh1,
                                    Wout, bout, out);
}